// round 7
// baseline (speedup 1.0000x reference)
#include <cuda_runtime.h>

// Problem constants
#define N    6144
#define T    1024           // threads per block
#define JPT  6              // j-indices owned per thread (N / T)
#define GRID 148            // one block per SM, single wave
#define MAXR 48             // max rows per block (6144/148 -> 41 or 42)

// MUFU.EX2 forced via PTX (never the slow accurate exp2f polynomial).
__device__ __forceinline__ float ex2(float v) {
    float r;
    asm("ex2.approx.f32 %0, %1;" : "=f"(r) : "f"(v));
    return r;
}

// Dynamic SMEM overlay (~151 KB): K/V for the CURRENT phase live here instead
// of registers, freeing the RF for 2x occupancy (32 warps/SM).
struct Smem {
    float kv[6][N];       // [comp][s*T + t]; comp: kx,ky,kz,vx,vy,vz ; j = 6t+s
    float sg[MAXR][3];    // current phase's g rows, pre-scaled by log2(e)
    float y2[MAXR][3];    // (a2 @ v2) rows from phase A
    float red[32][17];    // per-warp partials (stride 17: conflict-free stage 2)
    float tot[16];        // block totals, [sum,ax,ay,az] per row slot
    float sinv[4];        // 1/rowsum per row slot
};

// Compute this thread's 6 K and V rows straight from x into SMEM (thread-major).
__device__ __forceinline__ void fill_kv(
    Smem& sm, const float* __restrict__ x,
    const float* __restrict__ wk, const float* __restrict__ bk,
    const float* __restrict__ wv, const float* __restrict__ bv, int t)
{
    float xs[3 * JPT];
    const float2* xp = (const float2*)(x + 3 * JPT * t);   // 8B-aligned
    #pragma unroll
    for (int q = 0; q < (3 * JPT) / 2; q++) {
        float2 f = xp[q];
        xs[2*q] = f.x; xs[2*q+1] = f.y;
    }
    #pragma unroll
    for (int s = 0; s < JPT; s++) {
        float X0 = xs[3*s], X1 = xs[3*s+1], X2 = xs[3*s+2];
        sm.kv[0][s*T+t] = bk[0] + wk[0]*X0 + wk[1]*X1 + wk[2]*X2;
        sm.kv[1][s*T+t] = bk[1] + wk[3]*X0 + wk[4]*X1 + wk[5]*X2;
        sm.kv[2][s*T+t] = bk[2] + wk[6]*X0 + wk[7]*X1 + wk[8]*X2;
        sm.kv[3][s*T+t] = bv[0] + wv[0]*X0 + wv[1]*X1 + wv[2]*X2;
        sm.kv[4][s*T+t] = bv[1] + wv[3]*X0 + wv[4]*X1 + wv[5]*X2;
        sm.kv[5][s*T+t] = bv[2] + wv[6]*X0 + wv[7]*X1 + wv[8]*X2;
    }
}

// g rows for the block's row range: combined (wA+wB), pre-scaled by log2(e).
__device__ __forceinline__ void fill_g(
    Smem& sm, const float* __restrict__ x,
    const float* __restrict__ wA, const float* __restrict__ bA,
    const float* __restrict__ wB, const float* __restrict__ bB,
    int r0, int nr, int t)
{
    const float LOG2E = 1.4426950408889634f;
    if (t < nr) {
        int i = r0 + t;
        float X0 = x[3*i], X1 = x[3*i+1], X2 = x[3*i+2];
        #pragma unroll
        for (int c = 0; c < 3; c++) {
            float v = (bA[c] + bB[c])
                    + (wA[c*3+0] + wB[c*3+0]) * X0
                    + (wA[c*3+1] + wB[c*3+1]) * X1
                    + (wA[c*3+2] + wB[c*3+2]) * X2;
            sm.sg[t][c] = v * LOG2E;
        }
    }
}

__global__ void __launch_bounds__(T, 1) fused_gqa_kernel(
    const float* __restrict__ x,
    const float* __restrict__ wq1, const float* __restrict__ bq1,
    const float* __restrict__ wq2, const float* __restrict__ bq2,
    const float* __restrict__ wq3, const float* __restrict__ bq3,
    const float* __restrict__ wq4, const float* __restrict__ bq4,
    const float* __restrict__ wk1, const float* __restrict__ bk1,
    const float* __restrict__ wk2, const float* __restrict__ bk2,
    const float* __restrict__ wv1, const float* __restrict__ bv1,
    const float* __restrict__ wv2, const float* __restrict__ bv2,
    const float* __restrict__ wb,  const float* __restrict__ bb,
    float* __restrict__ a_out,     // [N, N]
    float* __restrict__ b_out)     // [N, 3]
{
    extern __shared__ char raw[];
    Smem& sm = *reinterpret_cast<Smem*>(raw);

    const int t  = threadIdx.x;
    const int r0 = (int)(((long long)N * blockIdx.x) / GRID);
    const int r1 = (int)(((long long)N * (blockIdx.x + 1)) / GRID);
    const int nr = r1 - r0;

    // =======================================================================
    // Phase A: matrix 2 (g2 = lin(q3)+lin(q4), k2, v2) -> y2 rows in SMEM.
    // 4 rows per iteration (16 reduced quantities).
    // =======================================================================
    fill_kv(sm, x, wk2, bk2, wv2, bv2, t);
    fill_g (sm, x, wq3, bq3, wq4, bq4, r0, nr, t);
    __syncthreads();

    for (int ii = 0; ii < nr; ii += 4) {
        int li[4];
        li[0] = ii;
        #pragma unroll
        for (int rr = 1; rr < 4; rr++) li[rr] = (ii + rr < nr) ? ii + rr : nr - 1;

        float g[4][3];
        #pragma unroll
        for (int rr = 0; rr < 4; rr++) {
            g[rr][0] = sm.sg[li[rr]][0];
            g[rr][1] = sm.sg[li[rr]][1];
            g[rr][2] = sm.sg[li[rr]][2];
        }

        float r[16];
        #pragma unroll
        for (int q = 0; q < 16; q++) r[q] = 0.f;

        #pragma unroll
        for (int s = 0; s < JPT; s++) {
            float kx = sm.kv[0][s*T+t], ky = sm.kv[1][s*T+t], kz = sm.kv[2][s*T+t];
            float vx = sm.kv[3][s*T+t], vy = sm.kv[4][s*T+t], vz = sm.kv[5][s*T+t];
            #pragma unroll
            for (int rr = 0; rr < 4; rr++) {
                float l = fmaf(g[rr][0], kx, fmaf(g[rr][1], ky, g[rr][2] * kz));
                float e = ex2(l);
                r[4*rr+0] += e;
                r[4*rr+1] = fmaf(e, vx, r[4*rr+1]);
                r[4*rr+2] = fmaf(e, vy, r[4*rr+2]);
                r[4*rr+3] = fmaf(e, vz, r[4*rr+3]);
            }
        }
        #pragma unroll
        for (int o = 16; o > 0; o >>= 1) {
            #pragma unroll
            for (int q = 0; q < 16; q++) r[q] += __shfl_xor_sync(0xffffffffu, r[q], o);
        }
        if ((t & 31) == 0) {
            int w = t >> 5;
            #pragma unroll
            for (int q = 0; q < 16; q++) sm.red[w][q] = r[q];
        }
        __syncthreads();
        if (t < 16 * 32) {                  // stage 2: warp q reduces 32 partials
            int q = t >> 5, w = t & 31;
            float v = sm.red[w][q];
            #pragma unroll
            for (int o = 16; o > 0; o >>= 1) v += __shfl_xor_sync(0xffffffffu, v, o);
            if (w == 0) {
                sm.tot[q] = v;
                if ((q & 3) == 0) sm.sinv[q >> 2] = 1.0f / v;
            }
        }
        __syncthreads();
        if ((t & 31) == 0 && (t >> 5) < 4) {
            int rr = t >> 5;
            if (ii + rr < nr) {
                float inv = sm.sinv[rr];
                sm.y2[ii+rr][0] = sm.tot[4*rr+1] * inv;
                sm.y2[ii+rr][1] = sm.tot[4*rr+2] * inv;
                sm.y2[ii+rr][2] = sm.tot[4*rr+3] * inv;
            }
        }
    }
    __syncthreads();   // all K/V reads of phase A done before overwrite

    // =======================================================================
    // Phase B: matrix 1 (g1 = lin(q1)+lin(q2), k1, v1) -> a1 rows + fused b.
    // 3 rows per iteration (12 reduced quantities), e kept in registers.
    // =======================================================================
    fill_kv(sm, x, wk1, bk1, wv1, bv1, t);
    fill_g (sm, x, wq1, bq1, wq2, bq2, r0, nr, t);
    __syncthreads();

    for (int ii = 0; ii < nr; ii += 3) {
        int li[3];
        li[0] = ii;
        #pragma unroll
        for (int rr = 1; rr < 3; rr++) li[rr] = (ii + rr < nr) ? ii + rr : nr - 1;

        float g[3][3];
        #pragma unroll
        for (int rr = 0; rr < 3; rr++) {
            g[rr][0] = sm.sg[li[rr]][0];
            g[rr][1] = sm.sg[li[rr]][1];
            g[rr][2] = sm.sg[li[rr]][2];
        }

        float ea[JPT], eb[JPT], ec[JPT];
        float r[12];
        #pragma unroll
        for (int q = 0; q < 12; q++) r[q] = 0.f;

        #pragma unroll
        for (int s = 0; s < JPT; s++) {
            float kx = sm.kv[0][s*T+t], ky = sm.kv[1][s*T+t], kz = sm.kv[2][s*T+t];
            float vx = sm.kv[3][s*T+t], vy = sm.kv[4][s*T+t], vz = sm.kv[5][s*T+t];

            float l0 = fmaf(g[0][0], kx, fmaf(g[0][1], ky, g[0][2] * kz));
            float l1 = fmaf(g[1][0], kx, fmaf(g[1][1], ky, g[1][2] * kz));
            float l2 = fmaf(g[2][0], kx, fmaf(g[2][1], ky, g[2][2] * kz));
            float e0 = ex2(l0), e1 = ex2(l1), e2 = ex2(l2);
            ea[s] = e0; eb[s] = e1; ec[s] = e2;
            r[0] += e0;                    r[4] += e1;                    r[8]  += e2;
            r[1] = fmaf(e0, vx, r[1]);     r[5] = fmaf(e1, vx, r[5]);     r[9]  = fmaf(e2, vx, r[9]);
            r[2] = fmaf(e0, vy, r[2]);     r[6] = fmaf(e1, vy, r[6]);     r[10] = fmaf(e2, vy, r[10]);
            r[3] = fmaf(e0, vz, r[3]);     r[7] = fmaf(e1, vz, r[7]);     r[11] = fmaf(e2, vz, r[11]);
        }
        #pragma unroll
        for (int o = 16; o > 0; o >>= 1) {
            #pragma unroll
            for (int q = 0; q < 12; q++) r[q] += __shfl_xor_sync(0xffffffffu, r[q], o);
        }
        if ((t & 31) == 0) {
            int w = t >> 5;
            #pragma unroll
            for (int q = 0; q < 12; q++) sm.red[w][q] = r[q];
        }
        __syncthreads();
        if (t < 12 * 32) {
            int q = t >> 5, w = t & 31;
            float v = sm.red[w][q];
            #pragma unroll
            for (int o = 16; o > 0; o >>= 1) v += __shfl_xor_sync(0xffffffffu, v, o);
            if (w == 0) {
                sm.tot[q] = v;
                if ((q & 3) == 0) sm.sinv[q >> 2] = 1.0f / v;
            }
        }
        __syncthreads();

        // Normalized a1 rows: 3x STG.64 per row per thread (j0 = 6t, 8B aligned).
        {
            const float inv0 = sm.sinv[0];
            float* dst = a_out + (size_t)(r0 + ii) * N + JPT * t;
            float2 o;
            o.x = ea[0]*inv0; o.y = ea[1]*inv0; ((float2*)dst)[0] = o;
            o.x = ea[2]*inv0; o.y = ea[3]*inv0; ((float2*)dst)[1] = o;
            o.x = ea[4]*inv0; o.y = ea[5]*inv0; ((float2*)dst)[2] = o;
        }
        if (ii + 1 < nr) {
            const float inv1 = sm.sinv[1];
            float* dst = a_out + (size_t)(r0 + ii + 1) * N + JPT * t;
            float2 o;
            o.x = eb[0]*inv1; o.y = eb[1]*inv1; ((float2*)dst)[0] = o;
            o.x = eb[2]*inv1; o.y = eb[3]*inv1; ((float2*)dst)[1] = o;
            o.x = eb[4]*inv1; o.y = eb[5]*inv1; ((float2*)dst)[2] = o;
        }
        if (ii + 2 < nr) {
            const float inv2 = sm.sinv[2];
            float* dst = a_out + (size_t)(r0 + ii + 2) * N + JPT * t;
            float2 o;
            o.x = ec[0]*inv2; o.y = ec[1]*inv2; ((float2*)dst)[0] = o;
            o.x = ec[2]*inv2; o.y = ec[3]*inv2; ((float2*)dst)[1] = o;
            o.x = ec[4]*inv2; o.y = ec[5]*inv2; ((float2*)dst)[2] = o;
        }
        // Fused final Linear: b_i = Wb((a1@v1)_i + y2_i) + bb  (one warp-lead/row)
        if ((t & 31) == 0 && (t >> 5) < 3) {
            int rr = t >> 5;
            if (ii + rr < nr) {
                int i = r0 + ii + rr;
                float inv = sm.sinv[rr];
                float y0 = sm.tot[4*rr+1] * inv + sm.y2[ii+rr][0];
                float y1 = sm.tot[4*rr+2] * inv + sm.y2[ii+rr][1];
                float y2 = sm.tot[4*rr+3] * inv + sm.y2[ii+rr][2];
                #pragma unroll
                for (int c = 0; c < 3; c++)
                    b_out[i*3+c] = bb[c] + wb[c*3+0]*y0 + wb[c*3+1]*y1 + wb[c*3+2]*y2;
            }
        }
    }
}

// ---------------------------------------------------------------------------
// Single launch. Output layout: a1 [N*N] followed by b [N*3].
// ---------------------------------------------------------------------------
extern "C" void kernel_launch(void* const* d_in, const int* in_sizes, int n_in,
                              void* d_out, int out_size)
{
    const float* x   = (const float*)d_in[0];
    const float* wq1 = (const float*)d_in[1];
    const float* bq1 = (const float*)d_in[2];
    const float* wq2 = (const float*)d_in[3];
    const float* bq2 = (const float*)d_in[4];
    const float* wq3 = (const float*)d_in[5];
    const float* bq3 = (const float*)d_in[6];
    const float* wq4 = (const float*)d_in[7];
    const float* bq4 = (const float*)d_in[8];
    const float* wk1 = (const float*)d_in[9];
    const float* bk1 = (const float*)d_in[10];
    const float* wk2 = (const float*)d_in[11];
    const float* bk2 = (const float*)d_in[12];
    const float* wv1 = (const float*)d_in[13];
    const float* bv1 = (const float*)d_in[14];
    const float* wv2 = (const float*)d_in[15];
    const float* bv2 = (const float*)d_in[16];
    const float* wb  = (const float*)d_in[17];
    const float* bb  = (const float*)d_in[18];

    float* out = (float*)d_out;
    float* a1  = out;                      // [N, N]
    float* b   = out + (size_t)N * N;      // [N, 3]

    // Host-side attribute set (immediate, not captured) for >48KB dynamic SMEM.
    cudaFuncSetAttribute(fused_gqa_kernel,
                         cudaFuncAttributeMaxDynamicSharedMemorySize,
                         (int)sizeof(Smem));

    fused_gqa_kernel<<<GRID, T, sizeof(Smem)>>>(
        x, wq1, bq1, wq2, bq2, wq3, bq3, wq4, bq4,
        wk1, bk1, wk2, bk2, wv1, bv1, wv2, bv2,
        wb, bb, a1, b);
}

// round 8
// speedup vs baseline: 1.0893x; 1.0893x over previous
#include <cuda_runtime.h>

// Problem constants
#define N     6144
#define GRID  148
#define MAXR  48
// Kernel P (reduce): 512 threads, 12 j's/thread, register-resident K+V.
#define TP    512
#define JP    12
// Kernel W (write): 1024 threads, 6 j's/thread, register-resident K only.
#define TW    1024
#define JW    6

// MUFU.EX2 forced via PTX.
__device__ __forceinline__ float ex2(float v) {
    float r;
    asm("ex2.approx.f32 %0, %1;" : "=f"(r) : "f"(v));
    return r;
}

// Per-row handoff P -> W: (g1x,g1y,g1z)*log2e in xyz, 1/rowsum in w.
__device__ float4 d_rowmeta[N];

struct SmemP {
    float sg[MAXR][3];    // current phase's g rows, pre-scaled by log2(e)
    float y2[MAXR][3];    // (a2 @ v2) rows from phase A
    float red[16][17];    // per-warp partials, stride 17 (conflict-free)
    float tot[16];        // block totals [sum,ax,ay,az] x 4 row slots
    float sinv[4];        // 1/rowsum per row slot
};

// ---------------------------------------------------------------------------
// Kernel P: both matrices, reduction-only (no a1 writes).
//   Phase A: g2/k2/v2 -> y2 rows (smem).
//   Phase B: g1/k1/v1 -> row sums + (e.v1); emits b_out and d_rowmeta.
//   K/V in registers (12 j's/thread); 4 rows per iteration.
// ---------------------------------------------------------------------------
__global__ void __launch_bounds__(TP, 1) reduce_kernel(
    const float* __restrict__ x,
    const float* __restrict__ wq1, const float* __restrict__ bq1,
    const float* __restrict__ wq2, const float* __restrict__ bq2,
    const float* __restrict__ wq3, const float* __restrict__ bq3,
    const float* __restrict__ wq4, const float* __restrict__ bq4,
    const float* __restrict__ wk1, const float* __restrict__ bk1,
    const float* __restrict__ wk2, const float* __restrict__ bk2,
    const float* __restrict__ wv1, const float* __restrict__ bv1,
    const float* __restrict__ wv2, const float* __restrict__ bv2,
    const float* __restrict__ wb,  const float* __restrict__ bb,
    float* __restrict__ b_out)     // [N, 3]
{
    __shared__ SmemP sm;

    const int t  = threadIdx.x;
    const int j0 = t * JP;
    const int r0 = (int)(((long long)N * blockIdx.x) / GRID);
    const int r1 = (int)(((long long)N * (blockIdx.x + 1)) / GRID);
    const int nr = r1 - r0;
    const float LOG2E = 1.4426950408889634f;

    float kx[JP], ky[JP], kz[JP], vx[JP], vy[JP], vz[JP];
    float xs[3 * JP];
    {   // x slice for this thread's j's (16B aligned: 144*t bytes)
        const float4* xp = (const float4*)(x + 3 * j0);
        #pragma unroll
        for (int q = 0; q < (3 * JP) / 4; q++) {
            float4 f = xp[q];
            xs[4*q] = f.x; xs[4*q+1] = f.y; xs[4*q+2] = f.z; xs[4*q+3] = f.w;
        }
    }

    #pragma unroll
    for (int phase = 0; phase < 2; phase++) {
        const float* wk = phase ? wk1 : wk2;  const float* bk = phase ? bk1 : bk2;
        const float* wv = phase ? wv1 : wv2;  const float* bv = phase ? bv1 : bv2;
        const float* wA = phase ? wq1 : wq3;  const float* bA = phase ? bq1 : bq3;
        const float* wB = phase ? wq2 : wq4;  const float* bB = phase ? bq2 : bq4;

        #pragma unroll
        for (int s = 0; s < JP; s++) {
            float X0 = xs[3*s], X1 = xs[3*s+1], X2 = xs[3*s+2];
            kx[s] = bk[0] + wk[0]*X0 + wk[1]*X1 + wk[2]*X2;
            ky[s] = bk[1] + wk[3]*X0 + wk[4]*X1 + wk[5]*X2;
            kz[s] = bk[2] + wk[6]*X0 + wk[7]*X1 + wk[8]*X2;
            vx[s] = bv[0] + wv[0]*X0 + wv[1]*X1 + wv[2]*X2;
            vy[s] = bv[1] + wv[3]*X0 + wv[4]*X1 + wv[5]*X2;
            vz[s] = bv[2] + wv[6]*X0 + wv[7]*X1 + wv[8]*X2;
        }
        if (t < nr) {
            int i = r0 + t;
            float X0 = x[3*i], X1 = x[3*i+1], X2 = x[3*i+2];
            #pragma unroll
            for (int c = 0; c < 3; c++) {
                float v = (bA[c] + bB[c])
                        + (wA[c*3+0] + wB[c*3+0]) * X0
                        + (wA[c*3+1] + wB[c*3+1]) * X1
                        + (wA[c*3+2] + wB[c*3+2]) * X2;
                sm.sg[t][c] = v * LOG2E;
            }
        }
        __syncthreads();

        for (int ii = 0; ii < nr; ii += 4) {
            int li[4];
            #pragma unroll
            for (int rr = 0; rr < 4; rr++) li[rr] = (ii + rr < nr) ? ii + rr : nr - 1;

            float g[4][3];
            #pragma unroll
            for (int rr = 0; rr < 4; rr++) {
                g[rr][0] = sm.sg[li[rr]][0];
                g[rr][1] = sm.sg[li[rr]][1];
                g[rr][2] = sm.sg[li[rr]][2];
            }

            float r[16];
            #pragma unroll
            for (int q = 0; q < 16; q++) r[q] = 0.f;

            #pragma unroll
            for (int s = 0; s < JP; s++) {
                float KX = kx[s], KY = ky[s], KZ = kz[s];
                float VX = vx[s], VY = vy[s], VZ = vz[s];
                #pragma unroll
                for (int rr = 0; rr < 4; rr++) {
                    float l = fmaf(g[rr][0], KX, fmaf(g[rr][1], KY, g[rr][2] * KZ));
                    float e = ex2(l);
                    r[4*rr+0] += e;
                    r[4*rr+1] = fmaf(e, VX, r[4*rr+1]);
                    r[4*rr+2] = fmaf(e, VY, r[4*rr+2]);
                    r[4*rr+3] = fmaf(e, VZ, r[4*rr+3]);
                }
            }
            #pragma unroll
            for (int o = 16; o > 0; o >>= 1) {
                #pragma unroll
                for (int q = 0; q < 16; q++)
                    r[q] += __shfl_xor_sync(0xffffffffu, r[q], o);
            }
            if ((t & 31) == 0) {
                int w = t >> 5;
                #pragma unroll
                for (int q = 0; q < 16; q++) sm.red[w][q] = r[q];
            }
            __syncthreads();
            {   // stage 2: warp q reduces the 16 per-warp partials of quantity q
                int q = t >> 5, w = t & 31;
                float v = (w < 16) ? sm.red[w][q] : 0.f;
                #pragma unroll
                for (int o = 8; o > 0; o >>= 1)
                    v += __shfl_xor_sync(0xffffffffu, v, o);
                if (w == 0) {
                    sm.tot[q] = v;
                    if ((q & 3) == 0) sm.sinv[q >> 2] = 1.0f / v;
                }
            }
            __syncthreads();

            if ((t & 31) == 0 && (t >> 5) < 4) {
                int rr = t >> 5;
                if (ii + rr < nr) {
                    float inv = sm.sinv[rr];
                    if (phase == 0) {
                        sm.y2[ii+rr][0] = sm.tot[4*rr+1] * inv;
                        sm.y2[ii+rr][1] = sm.tot[4*rr+2] * inv;
                        sm.y2[ii+rr][2] = sm.tot[4*rr+3] * inv;
                    } else {
                        int i = r0 + ii + rr;
                        // handoff to write kernel
                        float4 m;
                        m.x = sm.sg[ii+rr][0];
                        m.y = sm.sg[ii+rr][1];
                        m.z = sm.sg[ii+rr][2];
                        m.w = inv;
                        d_rowmeta[i] = m;
                        // fused final Linear: b_i = Wb((a1@v1)_i + y2_i) + bb
                        float y0 = sm.tot[4*rr+1] * inv + sm.y2[ii+rr][0];
                        float y1 = sm.tot[4*rr+2] * inv + sm.y2[ii+rr][1];
                        float y2 = sm.tot[4*rr+3] * inv + sm.y2[ii+rr][2];
                        #pragma unroll
                        for (int c = 0; c < 3; c++)
                            b_out[i*3+c] = bb[c] + wb[c*3+0]*y0
                                                 + wb[c*3+1]*y1
                                                 + wb[c*3+2]*y2;
                    }
                }
            }
            __syncthreads();
        }
        __syncthreads();   // phase A reads of sg/y2 complete before reuse
    }
}

// ---------------------------------------------------------------------------
// Kernel W: streaming a1 writer. Zero smem / shfl / barriers.
//   K1 only, in registers (18 regs). Per 4-row iteration: recompute e from
//   d_rowmeta (g pre-scaled, inv precomputed), scale, STG.64 out.
// ---------------------------------------------------------------------------
__global__ void __launch_bounds__(TW, 1) write_kernel(
    const float* __restrict__ x,
    const float* __restrict__ wk1, const float* __restrict__ bk1,
    float* __restrict__ a_out)     // [N, N]
{
    const int t  = threadIdx.x;
    const int j0 = t * JW;
    const int r0 = (int)(((long long)N * blockIdx.x) / GRID);
    const int r1 = (int)(((long long)N * (blockIdx.x + 1)) / GRID);
    const int nr = r1 - r0;

    float kx[JW], ky[JW], kz[JW];
    {
        float xs[3 * JW];
        const float2* xp = (const float2*)(x + 3 * j0);   // 72*t bytes, 8B aligned
        #pragma unroll
        for (int q = 0; q < (3 * JW) / 2; q++) {
            float2 f = xp[q];
            xs[2*q] = f.x; xs[2*q+1] = f.y;
        }
        #pragma unroll
        for (int s = 0; s < JW; s++) {
            float X0 = xs[3*s], X1 = xs[3*s+1], X2 = xs[3*s+2];
            kx[s] = bk1[0] + wk1[0]*X0 + wk1[1]*X1 + wk1[2]*X2;
            ky[s] = bk1[1] + wk1[3]*X0 + wk1[4]*X1 + wk1[5]*X2;
            kz[s] = bk1[2] + wk1[6]*X0 + wk1[7]*X1 + wk1[8]*X2;
        }
    }

    for (int ii = 0; ii < nr; ii += 4) {
        float4 m[4];
        int    iv[4];
        #pragma unroll
        for (int rr = 0; rr < 4; rr++) {
            int l = (ii + rr < nr) ? ii + rr : nr - 1;   // duplicate-row clamp
            iv[rr] = r0 + l;
            m[rr]  = d_rowmeta[iv[rr]];                  // broadcast LDG (L1/L2 hot)
        }
        #pragma unroll
        for (int rr = 0; rr < 4; rr++) {
            const float gx = m[rr].x, gy = m[rr].y, gz = m[rr].z, inv = m[rr].w;
            float2* dst = (float2*)(a_out + (size_t)iv[rr] * N + j0);
            #pragma unroll
            for (int q = 0; q < JW / 2; q++) {
                float l0 = fmaf(gx, kx[2*q+0], fmaf(gy, ky[2*q+0], gz * kz[2*q+0]));
                float l1 = fmaf(gx, kx[2*q+1], fmaf(gy, ky[2*q+1], gz * kz[2*q+1]));
                float2 o;
                o.x = ex2(l0) * inv;
                o.y = ex2(l1) * inv;
                dst[q] = o;
            }
        }
    }
}

// ---------------------------------------------------------------------------
// Two launches: reduce (y2, b, rowmeta) -> write (a1).
// Output layout: a1 [N*N] followed by b [N*3].
// ---------------------------------------------------------------------------
extern "C" void kernel_launch(void* const* d_in, const int* in_sizes, int n_in,
                              void* d_out, int out_size)
{
    const float* x   = (const float*)d_in[0];
    const float* wq1 = (const float*)d_in[1];
    const float* bq1 = (const float*)d_in[2];
    const float* wq2 = (const float*)d_in[3];
    const float* bq2 = (const float*)d_in[4];
    const float* wq3 = (const float*)d_in[5];
    const float* bq3 = (const float*)d_in[6];
    const float* wq4 = (const float*)d_in[7];
    const float* bq4 = (const float*)d_in[8];
    const float* wk1 = (const float*)d_in[9];
    const float* bk1 = (const float*)d_in[10];
    const float* wk2 = (const float*)d_in[11];
    const float* bk2 = (const float*)d_in[12];
    const float* wv1 = (const float*)d_in[13];
    const float* bv1 = (const float*)d_in[14];
    const float* wv2 = (const float*)d_in[15];
    const float* bv2 = (const float*)d_in[16];
    const float* wb  = (const float*)d_in[17];
    const float* bb  = (const float*)d_in[18];

    float* out = (float*)d_out;
    float* a1  = out;                      // [N, N]
    float* b   = out + (size_t)N * N;      // [N, 3]

    reduce_kernel<<<GRID, TP>>>(
        x, wq1, bq1, wq2, bq2, wq3, bq3, wq4, bq4,
        wk1, bk1, wk2, bk2, wv1, bv1, wv2, bv2,
        wb, bb, b);

    write_kernel<<<GRID, TW>>>(x, wk1, bk1, a1);
}

// round 9
// speedup vs baseline: 1.5066x; 1.3831x over previous
#include <cuda_runtime.h>

// Problem constants
#define N     6144
#define GRID  148
#define MAXR  48
// Kernel P (reduce): 512 threads, 12 j's/thread, register-resident K+V.
#define TP    512
#define JP    12
// Kernel W (write): 1024 threads, 3 j-PAIRS/thread (interleaved), K only.
#define TW    1024

// MUFU.EX2 forced via PTX.
__device__ __forceinline__ float ex2(float v) {
    float r;
    asm("ex2.approx.f32 %0, %1;" : "=f"(r) : "f"(v));
    return r;
}

// Per-row handoff P -> W: (g1x,g1y,g1z)*log2e in xyz, 1/rowsum in w.
__device__ float4 d_rowmeta[N];

struct SmemP {
    float sg[MAXR][3];       // current phase's g rows, pre-scaled by log2(e)
    float y2[MAXR][3];       // (a2 @ v2) rows from phase A
    float red[2][16][17];    // parity-buffered per-warp partials
    float tot[2][16];        // parity-buffered block totals
    float sinv[2][4];        // parity-buffered 1/rowsum
};

// ---------------------------------------------------------------------------
// Kernel P: both matrices, reduction-only (no a1 writes).
//   Phase A: g2/k2/v2 -> y2 rows (smem).
//   Phase B: g1/k1/v1 -> row sums + (e.v1); emits b_out and d_rowmeta.
//   K/V in registers (12 j's/thread); 4 rows/iter; 2 barriers/iter (parity).
// ---------------------------------------------------------------------------
__global__ void __launch_bounds__(TP, 1) reduce_kernel(
    const float* __restrict__ x,
    const float* __restrict__ wq1, const float* __restrict__ bq1,
    const float* __restrict__ wq2, const float* __restrict__ bq2,
    const float* __restrict__ wq3, const float* __restrict__ bq3,
    const float* __restrict__ wq4, const float* __restrict__ bq4,
    const float* __restrict__ wk1, const float* __restrict__ bk1,
    const float* __restrict__ wk2, const float* __restrict__ bk2,
    const float* __restrict__ wv1, const float* __restrict__ bv1,
    const float* __restrict__ wv2, const float* __restrict__ bv2,
    const float* __restrict__ wb,  const float* __restrict__ bb,
    float* __restrict__ b_out)     // [N, 3]
{
    __shared__ SmemP sm;

    const int t  = threadIdx.x;
    const int j0 = t * JP;
    const int r0 = (int)(((long long)N * blockIdx.x) / GRID);
    const int r1 = (int)(((long long)N * (blockIdx.x + 1)) / GRID);
    const int nr = r1 - r0;
    const float LOG2E = 1.4426950408889634f;

    float kx[JP], ky[JP], kz[JP], vx[JP], vy[JP], vz[JP];
    float xs[3 * JP];
    {   // x slice for this thread's j's (16B aligned: 144*t bytes)
        const float4* xp = (const float4*)(x + 3 * j0);
        #pragma unroll
        for (int q = 0; q < (3 * JP) / 4; q++) {
            float4 f = xp[q];
            xs[4*q] = f.x; xs[4*q+1] = f.y; xs[4*q+2] = f.z; xs[4*q+3] = f.w;
        }
    }

    #pragma unroll
    for (int phase = 0; phase < 2; phase++) {
        const float* wk = phase ? wk1 : wk2;  const float* bk = phase ? bk1 : bk2;
        const float* wv = phase ? wv1 : wv2;  const float* bv = phase ? bv1 : bv2;
        const float* wA = phase ? wq1 : wq3;  const float* bA = phase ? bq1 : bq3;
        const float* wB = phase ? wq2 : wq4;  const float* bB = phase ? bq2 : bq4;

        #pragma unroll
        for (int s = 0; s < JP; s++) {
            float X0 = xs[3*s], X1 = xs[3*s+1], X2 = xs[3*s+2];
            kx[s] = bk[0] + wk[0]*X0 + wk[1]*X1 + wk[2]*X2;
            ky[s] = bk[1] + wk[3]*X0 + wk[4]*X1 + wk[5]*X2;
            kz[s] = bk[2] + wk[6]*X0 + wk[7]*X1 + wk[8]*X2;
            vx[s] = bv[0] + wv[0]*X0 + wv[1]*X1 + wv[2]*X2;
            vy[s] = bv[1] + wv[3]*X0 + wv[4]*X1 + wv[5]*X2;
            vz[s] = bv[2] + wv[6]*X0 + wv[7]*X1 + wv[8]*X2;
        }
        if (t < nr) {
            int i = r0 + t;
            float X0 = x[3*i], X1 = x[3*i+1], X2 = x[3*i+2];
            #pragma unroll
            for (int c = 0; c < 3; c++) {
                float v = (bA[c] + bB[c])
                        + (wA[c*3+0] + wB[c*3+0]) * X0
                        + (wA[c*3+1] + wB[c*3+1]) * X1
                        + (wA[c*3+2] + wB[c*3+2]) * X2;
                sm.sg[t][c] = v * LOG2E;
            }
        }
        __syncthreads();

        int par = 0;
        for (int ii = 0; ii < nr; ii += 4, par ^= 1) {
            int li[4];
            #pragma unroll
            for (int rr = 0; rr < 4; rr++) li[rr] = (ii + rr < nr) ? ii + rr : nr - 1;

            float g[4][3];
            #pragma unroll
            for (int rr = 0; rr < 4; rr++) {
                g[rr][0] = sm.sg[li[rr]][0];
                g[rr][1] = sm.sg[li[rr]][1];
                g[rr][2] = sm.sg[li[rr]][2];
            }

            float r[16];
            #pragma unroll
            for (int q = 0; q < 16; q++) r[q] = 0.f;

            #pragma unroll
            for (int s = 0; s < JP; s++) {
                float KX = kx[s], KY = ky[s], KZ = kz[s];
                float VX = vx[s], VY = vy[s], VZ = vz[s];
                #pragma unroll
                for (int rr = 0; rr < 4; rr++) {
                    float l = fmaf(g[rr][0], KX, fmaf(g[rr][1], KY, g[rr][2] * KZ));
                    float e = ex2(l);
                    r[4*rr+0] += e;
                    r[4*rr+1] = fmaf(e, VX, r[4*rr+1]);
                    r[4*rr+2] = fmaf(e, VY, r[4*rr+2]);
                    r[4*rr+3] = fmaf(e, VZ, r[4*rr+3]);
                }
            }
            #pragma unroll
            for (int o = 16; o > 0; o >>= 1) {
                #pragma unroll
                for (int q = 0; q < 16; q++)
                    r[q] += __shfl_xor_sync(0xffffffffu, r[q], o);
            }
            if ((t & 31) == 0) {
                int w = t >> 5;
                #pragma unroll
                for (int q = 0; q < 16; q++) sm.red[par][w][q] = r[q];
            }
            __syncthreads();
            {   // stage 2: warp q reduces the 16 per-warp partials of quantity q
                int q = t >> 5, w = t & 31;
                float v = (w < 16) ? sm.red[par][w][q] : 0.f;
                #pragma unroll
                for (int o = 8; o > 0; o >>= 1)
                    v += __shfl_xor_sync(0xffffffffu, v, o);
                if (w == 0) {
                    sm.tot[par][q] = v;
                    if ((q & 3) == 0) sm.sinv[par][q >> 2] = 1.0f / v;
                }
            }
            __syncthreads();

            if ((t & 31) == 0 && (t >> 5) < 4) {
                int rr = t >> 5;
                if (ii + rr < nr) {
                    float inv = sm.sinv[par][rr];
                    if (phase == 0) {
                        sm.y2[ii+rr][0] = sm.tot[par][4*rr+1] * inv;
                        sm.y2[ii+rr][1] = sm.tot[par][4*rr+2] * inv;
                        sm.y2[ii+rr][2] = sm.tot[par][4*rr+3] * inv;
                    } else {
                        int i = r0 + ii + rr;
                        float4 m;
                        m.x = sm.sg[ii+rr][0];
                        m.y = sm.sg[ii+rr][1];
                        m.z = sm.sg[ii+rr][2];
                        m.w = inv;
                        d_rowmeta[i] = m;
                        float y0 = sm.tot[par][4*rr+1] * inv + sm.y2[ii+rr][0];
                        float y1 = sm.tot[par][4*rr+2] * inv + sm.y2[ii+rr][1];
                        float y2 = sm.tot[par][4*rr+3] * inv + sm.y2[ii+rr][2];
                        #pragma unroll
                        for (int c = 0; c < 3; c++)
                            b_out[i*3+c] = bb[c] + wb[c*3+0]*y0
                                                 + wb[c*3+1]*y1
                                                 + wb[c*3+2]*y2;
                    }
                }
            }
            // NO trailing barrier: next iter uses the other parity buffers.
        }
        __syncthreads();   // phase A sg/y2 reads complete before phase B refills
    }
}

// ---------------------------------------------------------------------------
// Kernel W: streaming a1 writer. Zero smem / shfl / barriers.
//   INTERLEAVED ownership: thread t owns j-pairs {2t + s*2048, s=0..2}, so
//   every STG.64's lanes are 8B-consecutive -> perfect 128B wavefronts
//   (the previous blocked layout cost 3x L1 traffic).
//   Per 4-row iteration: recompute e from d_rowmeta, scale, __stcs out.
// ---------------------------------------------------------------------------
__global__ void __launch_bounds__(TW, 1) write_kernel(
    const float* __restrict__ x,
    const float* __restrict__ wk1, const float* __restrict__ bk1,
    float* __restrict__ a_out)     // [N, N]
{
    const int t  = threadIdx.x;
    const int r0 = (int)(((long long)N * blockIdx.x) / GRID);
    const int r1 = (int)(((long long)N * (blockIdx.x + 1)) / GRID);
    const int nr = r1 - r0;

    // K1 for the 6 owned j's: j = 2t + s*2048 + {0,1}, s = 0..2.
    float kx[6], ky[6], kz[6];
    #pragma unroll
    for (int s = 0; s < 3; s++) {
        int jbase = 2 * t + s * 2048;
        #pragma unroll
        for (int h = 0; h < 2; h++) {
            int j = jbase + h;
            float X0 = x[3*j], X1 = x[3*j+1], X2 = x[3*j+2];
            kx[2*s+h] = bk1[0] + wk1[0]*X0 + wk1[1]*X1 + wk1[2]*X2;
            ky[2*s+h] = bk1[1] + wk1[3]*X0 + wk1[4]*X1 + wk1[5]*X2;
            kz[2*s+h] = bk1[2] + wk1[6]*X0 + wk1[7]*X1 + wk1[8]*X2;
        }
    }

    for (int ii = 0; ii < nr; ii += 4) {
        float4 m[4];
        int    iv[4];
        #pragma unroll
        for (int rr = 0; rr < 4; rr++) {
            int l = (ii + rr < nr) ? ii + rr : nr - 1;   // clamp (benign dup)
            iv[rr] = r0 + l;
            m[rr]  = d_rowmeta[iv[rr]];                  // broadcast LDG
        }
        #pragma unroll
        for (int rr = 0; rr < 4; rr++) {
            const float gx = m[rr].x, gy = m[rr].y, gz = m[rr].z, inv = m[rr].w;
            float* rowp = a_out + (size_t)iv[rr] * N + 2 * t;
            #pragma unroll
            for (int s = 0; s < 3; s++) {
                float l0 = fmaf(gx, kx[2*s+0], fmaf(gy, ky[2*s+0], gz * kz[2*s+0]));
                float l1 = fmaf(gx, kx[2*s+1], fmaf(gy, ky[2*s+1], gz * kz[2*s+1]));
                float2 o;
                o.x = ex2(l0) * inv;
                o.y = ex2(l1) * inv;
                __stcs((float2*)(rowp + s * 2048), o);   // evict-first stream
            }
        }
    }
}

// ---------------------------------------------------------------------------
// Two launches: reduce (y2, b, rowmeta) -> write (a1).
// Output layout: a1 [N*N] followed by b [N*3].
// ---------------------------------------------------------------------------
extern "C" void kernel_launch(void* const* d_in, const int* in_sizes, int n_in,
                              void* d_out, int out_size)
{
    const float* x   = (const float*)d_in[0];
    const float* wq1 = (const float*)d_in[1];
    const float* bq1 = (const float*)d_in[2];
    const float* wq2 = (const float*)d_in[3];
    const float* bq2 = (const float*)d_in[4];
    const float* wq3 = (const float*)d_in[5];
    const float* bq3 = (const float*)d_in[6];
    const float* wq4 = (const float*)d_in[7];
    const float* bq4 = (const float*)d_in[8];
    const float* wk1 = (const float*)d_in[9];
    const float* bk1 = (const float*)d_in[10];
    const float* wk2 = (const float*)d_in[11];
    const float* bk2 = (const float*)d_in[12];
    const float* wv1 = (const float*)d_in[13];
    const float* bv1 = (const float*)d_in[14];
    const float* wv2 = (const float*)d_in[15];
    const float* bv2 = (const float*)d_in[16];
    const float* wb  = (const float*)d_in[17];
    const float* bb  = (const float*)d_in[18];

    float* out = (float*)d_out;
    float* a1  = out;                      // [N, N]
    float* b   = out + (size_t)N * N;      // [N, 3]

    reduce_kernel<<<GRID, TP>>>(
        x, wq1, bq1, wq2, bq2, wq3, bq3, wq4, bq4,
        wk1, bk1, wk2, bk2, wv1, bv1, wv2, bv2,
        wb, bb, b);

    write_kernel<<<GRID, TW>>>(x, wk1, bk1, a1);
}